// round 5
// baseline (speedup 1.0000x reference)
#include <cuda_runtime.h>

// Fixed-shape problem: logits [8,19,512,512] f32, target [8,512,512] (int32 on device)
#define NCLS 19
#define HW   262144           // 512*512
#define HW4  65536            // HW/4
#define CHW  (NCLS * HW)
#define NBLK 148              // 1 CTA per SM, one wave
#define NTHR 384              // 12 warps/SM, regs capped at 170

// Per-block partials: [0..18]=prob_sums, [19..37]=intersection, [38..56]=counts,
// [57]=sum w_t, [58]=sum w_t*log_pt, [59]=sum alpha*(1-pt)^2*log_pt
__device__ float    g_part[NBLK][64];
__device__ unsigned g_sem;     // zero-initialized; self-resetting

__device__ __forceinline__ float ex2f(float x){ float r; asm("ex2.approx.ftz.f32 %0,%1;":"=f"(r):"f"(x)); return r; }
__device__ __forceinline__ float lg2f(float x){ float r; asm("lg2.approx.ftz.f32 %0,%1;":"=f"(r):"f"(x)); return r; }
__device__ __forceinline__ float rcpf(float x){ float r; asm("rcp.approx.ftz.f32 %0,%1;":"=f"(r):"f"(x)); return r; }

#define L2E 1.44269504088896f
#define LN2 0.69314718055995f

__global__ void __launch_bounds__(NTHR, 1)
fdl_kernel(const float* __restrict__ logits,
           const int*   __restrict__ target,
           const float* __restrict__ cw,
           const float* __restrict__ fa,
           float*       __restrict__ out,
           int P4)
{
    __shared__ float s_cw[NCLS], s_fa[NCLS];
    __shared__ float s_red[64];
    __shared__ float s_fin[4][64];
    __shared__ bool  s_last;

    const int tid = threadIdx.x;
    if (tid < NCLS) { s_cw[tid] = cw[tid]; s_fa[tid] = fa[tid]; }
    if (tid < 64)   s_red[tid] = 0.f;
    __syncthreads();

    // Per-thread accumulators (register-resident, static indexing only)
    float ps[NCLS], inter[NCLS];
    unsigned cntp[(NCLS + 1) / 2];          // two u16 counts per reg
#pragma unroll
    for (int c = 0; c < NCLS; ++c) { ps[c] = 0.f; inter[c] = 0.f; }
#pragma unroll
    for (int c = 0; c < (NCLS + 1) / 2; ++c) cntp[c] = 0u;
    float aw = 0.f, anll = 0.f, afoc = 0.f;

    const int stride = NBLK * NTHR;
    for (int pix4 = blockIdx.x * NTHR + tid; pix4 < P4; pix4 += stride) {
        const int b   = pix4 >> 16;          // pix4 / HW4
        const int hw4 = pix4 & (HW4 - 1);
        const float4* base = (const float4*)(logits + (size_t)b * CHW) + hw4;

        // 19 vectorized class streams: 19 x LDG.128 in flight per thread
        float4 l[NCLS];
#pragma unroll
        for (int c = 0; c < NCLS; ++c)
            l[c] = __ldg(base + (size_t)c * HW4);

        const int4 t4 = __ldg((const int4*)target + pix4);

        // Per sub-pixel: softmax in exp2 domain.
        //   pt     = e_t * invS                (no ex2 on the dependent path)
        //   log_pt = lg2(pt) * ln2             (single lg2, no lg2(S))
#define PROC(COMP, TT)                                                        \
        do {                                                                  \
            float e[NCLS];                                                    \
            float S = 0.f;                                                    \
            _Pragma("unroll")                                                 \
            for (int c = 0; c < NCLS; ++c) {                                  \
                e[c] = ex2f(l[c].COMP * L2E);                                 \
                S += e[c];                                                    \
            }                                                                 \
            float et = e[0];                                                  \
            _Pragma("unroll")                                                 \
            for (int c = 1; c < NCLS; ++c) et = ((TT) == c) ? e[c] : et;      \
            const float invS   = rcpf(S);                                     \
            const float pt     = et * invS;                                   \
            const float log_pt = lg2f(pt) * LN2;                              \
            const float wt = s_cw[TT];                                        \
            const float at = s_fa[TT];                                        \
            aw  += wt;                                                        \
            anll = fmaf(wt, log_pt, anll);                                    \
            const float ptf = fmaxf(pt, 1e-8f);                               \
            const float om  = 1.f - ptf;                                      \
            afoc = fmaf(at * om * om, log_pt, afoc);                          \
            _Pragma("unroll")                                                 \
            for (int c = 0; c < NCLS; ++c) {                                  \
                const bool p = ((TT) == c);                                   \
                ps[c]    = fmaf(e[c], invS, ps[c]);                           \
                inter[c] += p ? pt : 0.f;                                     \
                cntp[c >> 1] += p ? (1u << ((c & 1) * 16)) : 0u;              \
            }                                                                 \
        } while (0)

        PROC(x, t4.x);
        PROC(y, t4.y);
        PROC(z, t4.z);
        PROC(w, t4.w);
#undef PROC
    }

    // ---- Block reduction: warp shuffles, then smem atomics (once per block) ----
    const unsigned full = 0xffffffffu;
    const bool lead = ((tid & 31) == 0);
#pragma unroll
    for (int c = 0; c < NCLS; ++c) {
        const unsigned cc = cntp[c >> 1];
        float v0 = ps[c], v1 = inter[c];
        float v2 = (float)((c & 1) ? (cc >> 16) : (cc & 0xffffu));
#pragma unroll
        for (int o = 16; o > 0; o >>= 1) {
            v0 += __shfl_down_sync(full, v0, o);
            v1 += __shfl_down_sync(full, v1, o);
            v2 += __shfl_down_sync(full, v2, o);
        }
        if (lead) {
            atomicAdd(&s_red[c], v0);
            atomicAdd(&s_red[NCLS + c], v1);
            atomicAdd(&s_red[2 * NCLS + c], v2);
        }
    }
    {
        float v0 = aw, v1 = anll, v2 = afoc;
#pragma unroll
        for (int o = 16; o > 0; o >>= 1) {
            v0 += __shfl_down_sync(full, v0, o);
            v1 += __shfl_down_sync(full, v1, o);
            v2 += __shfl_down_sync(full, v2, o);
        }
        if (lead) {
            atomicAdd(&s_red[57], v0);
            atomicAdd(&s_red[58], v1);
            atomicAdd(&s_red[59], v2);
        }
    }
    __syncthreads();

    if (tid < 64) g_part[blockIdx.x][tid] = s_red[tid];

    // ---- Last block performs the final reduction (deterministic order) ----
    __threadfence();
    if (tid == 0) s_last = (atomicAdd(&g_sem, 1u) == NBLK - 1);
    __syncthreads();
    if (!s_last) return;

    if (tid == 0) g_sem = 0;    // reset for next graph replay
    __threadfence();

    if (tid < 256) {
        const int v = tid & 63;
        const int slice = tid >> 6;          // 0..3
        float acc = 0.f;
        for (int bb = slice; bb < NBLK; bb += 4) acc += g_part[bb][v];
        s_fin[slice][v] = acc;
    }
    __syncthreads();
    if (tid < 64)
        s_fin[0][tid] = s_fin[0][tid] + s_fin[1][tid] + s_fin[2][tid] + s_fin[3][tid];
    __syncthreads();

    if (tid == 0) {
        const float Pf    = (float)P4 * 4.0f;
        const float ce    = -s_fin[0][58] / s_fin[0][57];
        const float focal = -s_fin[0][59] / Pf;

        float sw = 0.f;
#pragma unroll
        for (int c = 0; c < NCLS; ++c) sw += s_cw[c];
        sw = fmaxf(sw, 1e-8f);

        float dsum = 0.f;
#pragma unroll
        for (int c = 0; c < NCLS; ++c) {
            const float dice = (2.f * s_fin[0][NCLS + c] + 1.f)
                             / (s_fin[0][c] + s_fin[0][2 * NCLS + c] + 1.f);
            dsum += dice * (s_cw[c] / sw);
        }
        const float dice_loss = 1.f - dsum;
        out[0] = 0.4f * ce + 0.3f * focal + 0.3f * dice_loss;
    }
}

extern "C" void kernel_launch(void* const* d_in, const int* in_sizes, int n_in,
                              void* d_out, int out_size)
{
    const float* logits = (const float*)d_in[0];
    const int*   target = (const int*)d_in[1];
    const float* cw     = (const float*)d_in[2];
    const float* fa     = (const float*)d_in[3];
    float*       out    = (float*)d_out;

    const int P4 = in_sizes[1] / 4;   // (B*H*W)/4 = 524,288

    fdl_kernel<<<NBLK, NTHR>>>(logits, target, cw, fa, out, P4);
}

// round 6
// speedup vs baseline: 1.0387x; 1.0387x over previous
#include <cuda_runtime.h>

// Fixed-shape problem: logits [8,19,512,512] f32, target [8,512,512] (int32 on device)
#define NCLS 19
#define HW   262144           // 512*512
#define HW2  131072           // HW/2
#define CHW  (NCLS * HW)
#define NBLK 296              // 2 CTAs per SM
#define NTHR 256

// Per-block partials: [0..18]=prob_sums, [19..37]=intersection, [38..56]=counts,
// [57]=sum w_t, [58]=sum w_t*log_pt, [59]=sum alpha*(1-pt)^2*log_pt
__device__ float    g_part[NBLK][64];
__device__ unsigned g_sem;     // zero-initialized; self-resetting

__device__ __forceinline__ float ex2f(float x){ float r; asm("ex2.approx.ftz.f32 %0,%1;":"=f"(r):"f"(x)); return r; }
__device__ __forceinline__ float lg2f(float x){ float r; asm("lg2.approx.ftz.f32 %0,%1;":"=f"(r):"f"(x)); return r; }
__device__ __forceinline__ float rcpf(float x){ float r; asm("rcp.approx.ftz.f32 %0,%1;":"=f"(r):"f"(x)); return r; }

#define L2E 1.44269504088896f
#define LN2 0.69314718055995f

__global__ void __launch_bounds__(NTHR, 2)     // <=128 regs, 2 CTAs/SM, 16 warps/SM
fdl_kernel(const float* __restrict__ logits,
           const int*   __restrict__ target,
           const float* __restrict__ cw,
           const float* __restrict__ fa,
           float*       __restrict__ out,
           int P2)
{
    __shared__ float s_cw[NCLS], s_fa[NCLS];
    __shared__ float s_red[64];
    __shared__ float s_fin[4][64];
    __shared__ bool  s_last;

    const int tid = threadIdx.x;
    if (tid < NCLS) { s_cw[tid] = cw[tid]; s_fa[tid] = fa[tid]; }
    if (tid < 64)   s_red[tid] = 0.f;
    __syncthreads();

    // Per-thread accumulators (register-resident, static indexing only)
    float ps[NCLS], inter[NCLS];
    unsigned cntp[(NCLS + 1) / 2];          // two u16 counts per reg
#pragma unroll
    for (int c = 0; c < NCLS; ++c) { ps[c] = 0.f; inter[c] = 0.f; }
#pragma unroll
    for (int c = 0; c < (NCLS + 1) / 2; ++c) cntp[c] = 0u;
    float aw = 0.f, anll = 0.f, afoc = 0.f;

    const int stride = NBLK * NTHR;
    for (int pix2 = blockIdx.x * NTHR + tid; pix2 < P2; pix2 += stride) {
        const int b   = pix2 >> 17;          // pix2 / HW2
        const int hw2 = pix2 & (HW2 - 1);
        const float2* base = (const float2*)(logits + (size_t)b * CHW) + hw2;

        // 19 vectorized class streams: 19 x LDG.64 in flight per thread.
        // Overwrite with exp2 values immediately (keeps live state at 38 regs).
        float2 e[NCLS];
        float  Sx = 0.f, Sy = 0.f;
#pragma unroll
        for (int c = 0; c < NCLS; ++c) {
            float2 v = __ldg(base + (size_t)c * HW2);
            e[c].x = ex2f(v.x * L2E);
            e[c].y = ex2f(v.y * L2E);
            Sx += e[c].x;
            Sy += e[c].y;
        }

        const int2 t2 = __ldg((const int2*)target + pix2);
        const float invSx = rcpf(Sx);
        const float invSy = rcpf(Sy);

#pragma unroll
        for (int c = 0; c < NCLS; ++c)
            ps[c] = fmaf(e[c].x, invSx, fmaf(e[c].y, invSy, ps[c]));

#define PROC(COMP, TT, INVS)                                                  \
        do {                                                                  \
            float et = e[0].COMP;                                             \
            _Pragma("unroll")                                                 \
            for (int c = 1; c < NCLS; ++c) et = ((TT) == c) ? e[c].COMP : et; \
            const float pt     = et * (INVS);                                 \
            const float log_pt = lg2f(pt) * LN2;                              \
            const float wt = s_cw[TT];                                        \
            const float at = s_fa[TT];                                        \
            aw  += wt;                                                        \
            anll = fmaf(wt, log_pt, anll);                                    \
            const float ptf = fmaxf(pt, 1e-8f);                               \
            const float om  = 1.f - ptf;                                      \
            afoc = fmaf(at * om * om, log_pt, afoc);                          \
            _Pragma("unroll")                                                 \
            for (int c = 0; c < NCLS; ++c) {                                  \
                const bool p = ((TT) == c);                                   \
                inter[c] += p ? pt : 0.f;                                     \
                cntp[c >> 1] += p ? (1u << ((c & 1) * 16)) : 0u;              \
            }                                                                 \
        } while (0)

        PROC(x, t2.x, invSx);
        PROC(y, t2.y, invSy);
#undef PROC
    }

    // ---- Block reduction: warp shuffles, then smem atomics (once per block) ----
    const unsigned full = 0xffffffffu;
    const bool lead = ((tid & 31) == 0);
#pragma unroll
    for (int c = 0; c < NCLS; ++c) {
        const unsigned cc = cntp[c >> 1];
        float v0 = ps[c], v1 = inter[c];
        float v2 = (float)((c & 1) ? (cc >> 16) : (cc & 0xffffu));
#pragma unroll
        for (int o = 16; o > 0; o >>= 1) {
            v0 += __shfl_down_sync(full, v0, o);
            v1 += __shfl_down_sync(full, v1, o);
            v2 += __shfl_down_sync(full, v2, o);
        }
        if (lead) {
            atomicAdd(&s_red[c], v0);
            atomicAdd(&s_red[NCLS + c], v1);
            atomicAdd(&s_red[2 * NCLS + c], v2);
        }
    }
    {
        float v0 = aw, v1 = anll, v2 = afoc;
#pragma unroll
        for (int o = 16; o > 0; o >>= 1) {
            v0 += __shfl_down_sync(full, v0, o);
            v1 += __shfl_down_sync(full, v1, o);
            v2 += __shfl_down_sync(full, v2, o);
        }
        if (lead) {
            atomicAdd(&s_red[57], v0);
            atomicAdd(&s_red[58], v1);
            atomicAdd(&s_red[59], v2);
        }
    }
    __syncthreads();

    if (tid < 64) g_part[blockIdx.x][tid] = s_red[tid];

    // ---- Last block performs the final reduction (deterministic order) ----
    __threadfence();
    if (tid == 0) s_last = (atomicAdd(&g_sem, 1u) == NBLK - 1);
    __syncthreads();
    if (!s_last) return;

    if (tid == 0) g_sem = 0;    // reset for next graph replay
    __threadfence();

    {
        const int v = tid & 63;
        const int slice = tid >> 6;          // 0..3
        float acc = 0.f;
        for (int bb = slice; bb < NBLK; bb += 4) acc += g_part[bb][v];
        s_fin[slice][v] = acc;
    }
    __syncthreads();
    if (tid < 64)
        s_fin[0][tid] = s_fin[0][tid] + s_fin[1][tid] + s_fin[2][tid] + s_fin[3][tid];
    __syncthreads();

    if (tid == 0) {
        const float Pf    = (float)P2 * 2.0f;
        const float ce    = -s_fin[0][58] / s_fin[0][57];
        const float focal = -s_fin[0][59] / Pf;

        float sw = 0.f;
#pragma unroll
        for (int c = 0; c < NCLS; ++c) sw += s_cw[c];
        sw = fmaxf(sw, 1e-8f);

        float dsum = 0.f;
#pragma unroll
        for (int c = 0; c < NCLS; ++c) {
            const float dice = (2.f * s_fin[0][NCLS + c] + 1.f)
                             / (s_fin[0][c] + s_fin[0][2 * NCLS + c] + 1.f);
            dsum += dice * (s_cw[c] / sw);
        }
        const float dice_loss = 1.f - dsum;
        out[0] = 0.4f * ce + 0.3f * focal + 0.3f * dice_loss;
    }
}

extern "C" void kernel_launch(void* const* d_in, const int* in_sizes, int n_in,
                              void* d_out, int out_size)
{
    const float* logits = (const float*)d_in[0];
    const int*   target = (const int*)d_in[1];
    const float* cw     = (const float*)d_in[2];
    const float* fa     = (const float*)d_in[3];
    float*       out    = (float*)d_out;

    const int P2 = in_sizes[1] / 2;   // (B*H*W)/2 = 1,048,576

    fdl_kernel<<<NBLK, NTHR>>>(logits, target, cw, fa, out, P2);
}